// round 3
// baseline (speedup 1.0000x reference)
#include <cuda_runtime.h>
#include <math.h>

#define NUM_CLASSES 16
#define MARGIN 0.3f
#define EPS 1e-8f
#define INVALID 0x7fffffff

// ---------------- device-global scratch ----------------
__device__ int   g_present[NUM_CLASSES];
__device__ int   g_ua64;
__device__ float g_D[NUM_CLASSES * NUM_CLASSES];
__device__ float g_sum_rank;
__device__ float g_sum_per;
__device__ int   g_cnt;
__device__ unsigned g_done;

// Dedup-min update: within one load slot, the global index = base + tid is
// strictly increasing with lane, so the lowest-lane peer holding a given class
// value owns the minimum index among its warp's matches.
__device__ __forceinline__ void first_update(unsigned w, int i, int* s_first) {
    unsigned peers = __match_any_sync(0xffffffffu, w);
    int leader = __ffs(peers) - 1;
    if (((int)(threadIdx.x & 31) == leader) && w < (unsigned)NUM_CLASSES)
        atomicMin(&s_first[w], i);
}

// ---------------- K_A: first_idx scan + one D row per block ----------------
// Grid: 16 blocks x 1024 threads. Each block scans targets_mat itself (the
// scan is latency-bound; 16 parallel redundant scans cost one scan of wall
// time), then block i computes D[i][0..15].
__global__ __launch_bounds__(1024) void kA(const float* __restrict__ inputs,
                                           const void* __restrict__ tm,
                                           const void* __restrict__ ua,
                                           int n_tm, int n_ua_elems, int D) {
    __shared__ int   s_first[NUM_CLASSES];
    __shared__ int   s_tm64, s_ua64;
    __shared__ float s_part[32][NUM_CLASSES + 1];   // +1 pad vs bank conflicts

    int tid = threadIdx.x;
    if (tid < NUM_CLASSES) s_first[tid] = INVALID;
    if (tid == 0) { s_tm64 = 1; s_ua64 = 1; }
    __syncthreads();

    const unsigned* tw = (const unsigned*)tm;
    const unsigned* uw = (const unsigned*)ua;

    // ---- dtype detection (values in [0,16): int64 => all odd words zero).
    {
        int lim_t = n_tm < 8192 ? n_tm : 8192;          // >= n_tm words exist
        unsigned v = 0u;
        #pragma unroll
        for (int r = 0; r < 4; r++) {
            int w = 2 * tid + 1 + r * 2048;
            if (w < lim_t) v |= tw[w];
        }
        if (v) s_tm64 = 0;
        if (blockIdx.x == 0) {
            int lim_u = n_ua_elems < 8192 ? n_ua_elems : 8192;
            unsigned vu = 0u;
            #pragma unroll
            for (int r = 0; r < 4; r++) {
                int w = 2 * tid + 1 + r * 2048;
                if (w < lim_u) vu |= uw[w];
            }
            if (vu) s_ua64 = 0;
        }
    }
    __syncthreads();
    int tm64 = s_tm64;

    // ---- first occurrence per class (front-batched loads, dedup'd atomics)
    for (int base = 0; base < n_tm; base += 4096) {
        int i0 = base + tid, i1 = i0 + 1024, i2 = i1 + 1024, i3 = i2 + 1024;
        unsigned w0 = ~0u, w1 = ~0u, w2 = ~0u, w3 = ~0u;
        if (tm64) {
            if (i0 < n_tm) w0 = tw[2 * i0];
            if (i1 < n_tm) w1 = tw[2 * i1];
            if (i2 < n_tm) w2 = tw[2 * i2];
            if (i3 < n_tm) w3 = tw[2 * i3];
        } else {
            if (i0 < n_tm) w0 = tw[i0];
            if (i1 < n_tm) w1 = tw[i1];
            if (i2 < n_tm) w2 = tw[i2];
            if (i3 < n_tm) w3 = tw[i3];
        }
        first_update(w0, i0, s_first);
        first_update(w1, i1, s_first);
        first_update(w2, i2, s_first);
        first_update(w3, i3, s_first);
    }
    __syncthreads();

    // ---- block 0 publishes presence/dtype and zeroes accumulators
    if (blockIdx.x == 0) {
        if (tid < NUM_CLASSES) g_present[tid] = (s_first[tid] != INVALID) ? 1 : 0;
        if (tid == 0) {
            g_ua64 = s_ua64;
            g_sum_rank = 0.0f; g_sum_per = 0.0f; g_cnt = 0; g_done = 0u;
        }
    }

    // ---- distance row i
    int fj[NUM_CLASSES];
    #pragma unroll
    for (int j = 0; j < NUM_CLASSES; j++) {
        int f = s_first[j];
        fj[j] = (f == INVALID) ? 0 : f;     // argmax over all-false row == 0
    }
    int fi = fj[blockIdx.x];

    float acc[NUM_CLASSES];
    #pragma unroll
    for (int j = 0; j < NUM_CLASSES; j++) acc[j] = 0.0f;

    for (int base = 0; base < D; base += 1024) {
        int k = base + tid;
        if (k < D) {
            float x = __ldg(inputs + (size_t)fi * D + k);
            float y[NUM_CLASSES];
            #pragma unroll
            for (int j = 0; j < NUM_CLASSES; j++)
                y[j] = __ldg(inputs + (size_t)fj[j] * D + k);
            #pragma unroll
            for (int j = 0; j < NUM_CLASSES; j++) {
                float d = x - y[j];
                acc[j] = fmaf(d, d, acc[j]);
            }
        }
    }

    // warp reduce each of 16 sums, then cross-warp via smem
    #pragma unroll
    for (int j = 0; j < NUM_CLASSES; j++) {
        float s = acc[j];
        #pragma unroll
        for (int o = 16; o > 0; o >>= 1) s += __shfl_xor_sync(0xffffffffu, s, o);
        acc[j] = s;
    }
    int w = tid >> 5;
    if ((tid & 31) == 0) {
        #pragma unroll
        for (int j = 0; j < NUM_CLASSES; j++) s_part[w][j] = acc[j];
    }
    __syncthreads();
    if (tid < NUM_CLASSES) {
        float s = 0.0f;
        #pragma unroll
        for (int k = 0; k < 32; k++) s += s_part[k][tid];
        g_D[blockIdx.x * NUM_CLASSES + tid] = sqrtf(fmaxf(s, 1e-12f));
    }
}

// ---------------- K_B: reduction over T triples + finalize ----------------
__global__ __launch_bounds__(256) void kB(const void* __restrict__ ua, int T,
                                          int nblocks, float* __restrict__ out) {
    __shared__ float sD[NUM_CLASSES * NUM_CLASSES];
    __shared__ int   sP[NUM_CLASSES];
    __shared__ float srk[8], spr[8];
    __shared__ int   sv[8];

    int tid = threadIdx.x;
    sD[tid] = g_D[tid];                       // 256 threads, 256 entries
    if (tid < NUM_CLASSES) sP[tid] = g_present[tid];
    __syncthreads();

    int t = blockIdx.x * blockDim.x + tid;
    float rk = 0.0f, pr = 0.0f;
    int v = 0;

    if (t < T) {
        int c0, c1, c2;
        if (g_ua64) {
            const long long* p = (const long long*)ua + (size_t)3 * t;
            c0 = (int)__ldg(p); c1 = (int)__ldg(p + 1); c2 = (int)__ldg(p + 2);
        } else {
            const int* p = (const int*)ua + (size_t)3 * t;
            c0 = __ldg(p); c1 = __ldg(p + 1); c2 = __ldg(p + 2);
        }
        bool inrange = ((unsigned)c0 < 16u) & ((unsigned)c1 < 16u) & ((unsigned)c2 < 16u);
        if (inrange && sP[c0] && sP[c1] && sP[c2]) {
            v = 1;
            float dap = sD[c0 * 16 + c1];
            float dan = sD[c0 * 16 + c2];
            rk = fmaxf(dap - dan + MARGIN, 0.0f);
            // s_ap/(s_ap+s_an) with s = 1/(d+1)  ==  (dan+1)/(dap+dan+2)
            float p_ap = __fdividef(dan + 1.0f, dap + dan + 2.0f);
            pr = -__logf(p_ap + EPS);
        }
    }

    #pragma unroll
    for (int o = 16; o > 0; o >>= 1) {
        rk += __shfl_xor_sync(0xffffffffu, rk, o);
        pr += __shfl_xor_sync(0xffffffffu, pr, o);
        v  += __shfl_xor_sync(0xffffffffu, v,  o);
    }

    int w = tid >> 5;
    if ((tid & 31) == 0) { srk[w] = rk; spr[w] = pr; sv[w] = v; }
    __syncthreads();

    if (tid == 0) {
        float R = 0.0f, P = 0.0f; int V = 0;
        #pragma unroll
        for (int k = 0; k < 8; k++) { R += srk[k]; P += spr[k]; V += sv[k]; }
        atomicAdd(&g_sum_rank, R);
        atomicAdd(&g_sum_per,  P);
        atomicAdd(&g_cnt,      V);
        __threadfence();
        unsigned d = atomicAdd(&g_done, 1u);
        if (d == (unsigned)(nblocks - 1)) {
            float sr  = atomicAdd(&g_sum_rank, 0.0f);
            float sp2 = atomicAdd(&g_sum_per,  0.0f);
            int   cn  = atomicAdd(&g_cnt,      0);
            float nv = fmaxf((float)cn, 1.0f);
            float lh = sr / nv;
            float lp = sp2 / nv;
            out[0] = lh + lp;
            out[1] = lh;
            out[2] = lp;
        }
    }
}

// ---------------- launch ----------------
// Inputs: 0 preds_mat(f32), 1 preds_sub(f32), 2 inputs(f32 B*D),
// 3 targets_mat(int, B), 4 targets_sub(int, B), 5 user_answers(int, T*3)
extern "C" void kernel_launch(void* const* d_in, const int* in_sizes, int n_in,
                              void* d_out, int out_size) {
    const float* inputs = (const float*)d_in[2];
    const void*  tm     = d_in[3];
    const void*  ua     = d_in[5];
    int n_tm = in_sizes[3];
    int n_ua = in_sizes[5];
    int T = n_ua / 3;
    int D = in_sizes[2] / n_tm;

    kA<<<NUM_CLASSES, 1024>>>(inputs, tm, ua, n_tm, n_ua, D);
    int nb = (T + 255) / 256;
    kB<<<nb, 256>>>(ua, T, nb, (float*)d_out);
}